// round 4
// baseline (speedup 1.0000x reference)
#include <cuda_runtime.h>
#include <cuda_bf16.h>

// Fixed problem shapes
#define NN      100000      // total nodes
#define EE      1600000     // total edges
#define EPG     32000       // edges per graph
#define NZZ     2400000     // framelet nnz
#define NZPG    48000       // nnz per graph
#define BB      50          // graphs
#define NPG     2000        // nodes per graph
#define BANDS   3
#define HH      64
#define CRR     6000        // coef rows per graph
#define CC      10

#define SCAN_B  1024
#define NBLK    ((NN + SCAN_B - 1) / SCAN_B)   // 98

// -------- scratch (static device globals) --------
__device__ float g_bufA[NN * HH];     // post-GEMM (dinv-scaled)
__device__ float g_bufB[NN * HH];     // post-aggregation (relu)
__device__ float g_dinv[NN];
__device__ int   g_cnt[NN];
__device__ int   g_rowptr[NN + 1];
__device__ int   g_cols[EE];
__device__ int   g_bsums[128];
__device__ float g_wnode[NN * BANDS]; // per-node per-band framelet weight
__device__ float g_pooled[BB * BANDS * HH];

// ---------------- zero the tiny pooled buffer ----------------
__global__ void k_zero_pooled() {
    int i = blockIdx.x * blockDim.x + threadIdx.x;
    if (i < BB * BANDS * HH) g_pooled[i] = 0.0f;
}

// ---------- per-graph degree histogram (smem atomics only) ----------
__global__ void __launch_bounds__(1024) k_hist(const int* __restrict__ row) {
    int g = blockIdx.x;
    __shared__ int cnt[NPG];
    for (int i = threadIdx.x; i < NPG; i += 1024) cnt[i] = 0;
    __syncthreads();
    int base = g * EPG;
    int nbase = g * NPG;
    for (int e = base + threadIdx.x; e < base + EPG; e += 1024)
        atomicAdd(&cnt[row[e] - nbase], 1);
    __syncthreads();
    for (int i = threadIdx.x; i < NPG; i += 1024) g_cnt[nbase + i] = cnt[i];
}

// ---------------- 2-level exclusive scan for CSR rowptr ----------------
__global__ void k_scan1() {
    __shared__ int s[SCAN_B];
    int i = blockIdx.x * SCAN_B + threadIdx.x;
    int v = (i < NN) ? g_cnt[i] : 0;
    s[threadIdx.x] = v;
    __syncthreads();
    for (int off = 1; off < SCAN_B; off <<= 1) {
        int t = (threadIdx.x >= off) ? s[threadIdx.x - off] : 0;
        __syncthreads();
        s[threadIdx.x] += t;
        __syncthreads();
    }
    if (i < NN) g_rowptr[i] = s[threadIdx.x] - v;  // exclusive within block
    if (threadIdx.x == SCAN_B - 1) g_bsums[blockIdx.x] = s[SCAN_B - 1];
}

__global__ void k_scan2() {
    __shared__ int s[128];
    int x = threadIdx.x;
    int v = (x < NBLK) ? g_bsums[x] : 0;
    s[x] = v;
    __syncthreads();
    for (int off = 1; off < 128; off <<= 1) {
        int t = (x >= off) ? s[x - off] : 0;
        __syncthreads();
        s[x] += t;
        __syncthreads();
    }
    if (x < NBLK) g_bsums[x] = s[x] - v;  // exclusive
}

__global__ void k_scan3() {
    int i = blockIdx.x * blockDim.x + threadIdx.x;
    if (i < NN) {
        int rp = g_rowptr[i] + g_bsums[i >> 10];
        g_rowptr[i] = rp;
        g_dinv[i]   = rsqrtf((float)(g_cnt[i] + 1));  // +1 self loop
    }
    if (i == 0) g_rowptr[NN] = EE;
}

// ---------- per-graph CSR scatter (smem cursors) ----------
__global__ void __launch_bounds__(1024) k_scatter(const int* __restrict__ row,
                                                  const int* __restrict__ col) {
    int g = blockIdx.x;
    __shared__ int cur[NPG];
    int nbase = g * NPG;
    for (int i = threadIdx.x; i < NPG; i += 1024) cur[i] = g_rowptr[nbase + i];
    __syncthreads();
    int base = g * EPG;
    for (int e = base + threadIdx.x; e < base + EPG; e += 1024) {
        int r = row[e] - nbase;
        int p = atomicAdd(&cur[r], 1);
        g_cols[p] = col[e];
    }
}

// ---------- per-graph framelet weight table (smem float atomics) ----------
__global__ void __launch_bounds__(1024) k_frame(const int* __restrict__ fr,
                                                const int* __restrict__ fc,
                                                const float* __restrict__ fv,
                                                const int* __restrict__ dix) {
    int g = blockIdx.x;
    __shared__ float w[NPG * BANDS];   // 24KB
    for (int i = threadIdx.x; i < NPG * BANDS; i += 1024) w[i] = 0.0f;
    __syncthreads();
    int base = g * NZPG;
    int nbase = g * NPG;
    for (int e = base + threadIdx.x; e < base + NZPG; e += 1024) {
        int r = fr[e];
        int c = fc[e] - nbase;
        float v = fv[e];
        int band = dix[r];
        atomicAdd(&w[c * BANDS + band], v);
    }
    __syncthreads();
    int obase = g * NPG * BANDS;
    for (int i = threadIdx.x; i < NPG * BANDS; i += 1024) g_wnode[obase + i] = w[i];
}

// -------- dense GEMM: C[r,:] = dinv[r] * (A[r,:] @ W) --------
__global__ void __launch_bounds__(256) k_gemm(const float* __restrict__ A,
                                              const float* __restrict__ W,
                                              float* __restrict__ C) {
    __shared__ float Ws[64][68];
    __shared__ float As[64][68];   // transposed: As[k][r]
    int tid = threadIdx.x;
    int r0 = blockIdx.x * 64;

    for (int idx = tid; idx < 4096; idx += 256) Ws[idx >> 6][idx & 63] = W[idx];
    for (int idx = tid; idx < 4096; idx += 256) {
        int r = idx >> 6, k = idx & 63;
        int gr = r0 + r;
        As[k][r] = (gr < NN) ? A[gr * 64 + k] : 0.0f;
    }
    __syncthreads();

    int tx = tid & 15, ty = tid >> 4;
    float acc[4][4];
#pragma unroll
    for (int i = 0; i < 4; i++)
#pragma unroll
        for (int j = 0; j < 4; j++) acc[i][j] = 0.0f;

#pragma unroll
    for (int k = 0; k < 64; k++) {
        float4 a = *(const float4*)(&As[k][ty * 4]);
        float4 w = *(const float4*)(&Ws[k][tx * 4]);
        float av[4] = {a.x, a.y, a.z, a.w};
        float wv[4] = {w.x, w.y, w.z, w.w};
#pragma unroll
        for (int i = 0; i < 4; i++)
#pragma unroll
            for (int j = 0; j < 4; j++) acc[i][j] += av[i] * wv[j];
    }

#pragma unroll
    for (int i = 0; i < 4; i++) {
        int gr = r0 + ty * 4 + i;
        if (gr < NN) {
            float d = g_dinv[gr];
            float4 o = make_float4(d * acc[i][0], d * acc[i][1],
                                   d * acc[i][2], d * acc[i][3]);
            *(float4*)(&C[gr * 64 + tx * 4]) = o;
        }
    }
}

// ------- GCN aggregation: warp per row; input already dinv-scaled -------
// out[r] = relu( dinv[r] * ( hd[r] + sum_c hd[c] ) + b )
__global__ void __launch_bounds__(256) k_agg(const float* __restrict__ hd,
                                             const float* __restrict__ bias,
                                             float* __restrict__ hout) {
    int gw = (blockIdx.x * blockDim.x + threadIdx.x) >> 5;
    int lane = threadIdx.x & 31;
    if (gw >= NN) return;
    int r = gw;
    float dr = g_dinv[r];
    const float2* h2 = (const float2*)hd;

    float2 hv = h2[r * 32 + lane];        // self loop (already *dinv[r])
    float ax = hv.x, ay = hv.y;

    int e0 = g_rowptr[r], e1 = g_rowptr[r + 1];
    int e = e0;
    for (; e + 4 <= e1; e += 4) {
        int c0 = g_cols[e + 0];
        int c1 = g_cols[e + 1];
        int c2 = g_cols[e + 2];
        int c3 = g_cols[e + 3];
        float2 h0 = h2[c0 * 32 + lane];
        float2 h1 = h2[c1 * 32 + lane];
        float2 hc2 = h2[c2 * 32 + lane];
        float2 hc3 = h2[c3 * 32 + lane];
        ax += h0.x + h1.x + hc2.x + hc3.x;
        ay += h0.y + h1.y + hc2.y + hc3.y;
    }
    for (; e < e1; e++) {
        int c = g_cols[e];
        float2 hc = h2[c * 32 + lane];
        ax += hc.x;
        ay += hc.y;
    }
    float bx = bias[lane * 2];
    float by = bias[lane * 2 + 1];
    ((float2*)hout)[r * 32 + lane] =
        make_float2(fmaxf(dr * ax + bx, 0.0f), fmaxf(dr * ay + by, 0.0f));
}

// ------- pooled[g,band,:] = sum_j wnode[j,band]*h[j,:] -------
#define POOL_CHUNKS 8
__global__ void __launch_bounds__(256) k_pool(const float* __restrict__ h) {
    int g = blockIdx.x / POOL_CHUNKS;
    int chunk = blockIdx.x % POOL_CHUNKS;
    int f = threadIdx.x & 63;
    int sub = threadIdx.x >> 6;
    int base = g * NPG + chunk * (NPG / POOL_CHUNKS);
    int end = base + (NPG / POOL_CHUNKS);

    float a0 = 0.0f, a1 = 0.0f, a2 = 0.0f;
    for (int j = base + sub; j < end; j += 4) {
        float w0 = g_wnode[j * 3 + 0];
        float w1 = g_wnode[j * 3 + 1];
        float w2 = g_wnode[j * 3 + 2];
        float hv = h[j * 64 + f];
        a0 += w0 * hv;
        a1 += w1 * hv;
        a2 += w2 * hv;
    }
    __shared__ float s[4][3][64];
    s[sub][0][f] = a0;
    s[sub][1][f] = a1;
    s[sub][2][f] = a2;
    __syncthreads();
    if (sub == 0) {
#pragma unroll
        for (int b = 0; b < 3; b++) {
            float t = s[0][b][f] + s[1][b][f] + s[2][b][f] + s[3][b][f];
            atomicAdd(&g_pooled[(g * 3 + b) * 64 + f], t);
        }
    }
}

// ------- MLP head -------
__global__ void __launch_bounds__(64) k_head(const float* __restrict__ fcW1,
                                             const float* __restrict__ fcb1,
                                             const float* __restrict__ fcW2,
                                             const float* __restrict__ fcb2,
                                             float* __restrict__ out) {
    int g = blockIdx.x;
    int t = threadIdx.x;
    __shared__ float xp[BANDS * HH];
    __shared__ float hid[HH];
    for (int i = t; i < BANDS * HH; i += 64) xp[i] = g_pooled[g * (BANDS * HH) + i];
    __syncthreads();
    float acc = fcb1[t];
#pragma unroll 8
    for (int k = 0; k < BANDS * HH; k++) acc += xp[k] * fcW1[k * 64 + t];
    hid[t] = fmaxf(acc, 0.0f);
    __syncthreads();
    if (t < CC) {
        float o = fcb2[t];
#pragma unroll
        for (int k = 0; k < HH; k++) o += hid[k] * fcW2[k * CC + t];
        out[g * CC + t] = o;
    }
}

extern "C" void kernel_launch(void* const* d_in, const int* in_sizes, int n_in,
                              void* d_out, int out_size) {
    (void)in_sizes; (void)n_in; (void)out_size;
    const float* x    = (const float*)d_in[0];
    const int*   ei   = (const int*)d_in[1];
    const int*   frow = (const int*)d_in[3];
    const int*   fcol = (const int*)d_in[4];
    const float* fval = (const float*)d_in[5];
    const int*   dix  = (const int*)d_in[6];
    const float* W1   = (const float*)d_in[8];
    const float* b1   = (const float*)d_in[9];
    const float* W2   = (const float*)d_in[10];
    const float* b2   = (const float*)d_in[11];
    const float* fcW1 = (const float*)d_in[12];
    const float* fcb1 = (const float*)d_in[13];
    const float* fcW2 = (const float*)d_in[14];
    const float* fcb2 = (const float*)d_in[15];
    float* out = (float*)d_out;

    const int* row = ei;        // edge_index[0]
    const int* col = ei + EE;   // edge_index[1]

    k_zero_pooled<<<(BB * BANDS * HH + 255) / 256, 256>>>();
    k_hist<<<BB, 1024>>>(row);
    k_scan1<<<NBLK, SCAN_B>>>();
    k_scan2<<<1, 128>>>();
    k_scan3<<<(NN + 255) / 256, 256>>>();
    k_scatter<<<BB, 1024>>>(row, col);
    k_frame<<<BB, 1024>>>(frow, fcol, fval, dix);

    k_gemm<<<(NN + 63) / 64, 256>>>(x, W1, g_bufA);
    k_agg<<<(NN * 32 + 255) / 256, 256>>>(g_bufA, b1, g_bufB);
    k_gemm<<<(NN + 63) / 64, 256>>>(g_bufB, W2, g_bufA);
    k_agg<<<(NN * 32 + 255) / 256, 256>>>(g_bufA, b2, g_bufB);

    k_pool<<<BB * POOL_CHUNKS, 256>>>(g_bufB);
    k_head<<<BB, 64>>>(fcW1, fcb1, fcW2, fcb2, out);
}

// round 6
// speedup vs baseline: 11.6274x; 11.6274x over previous
#include <cuda_runtime.h>
#include <cuda_bf16.h>

// Fixed problem shapes
#define NN      100000      // total nodes
#define EE      1600000     // total edges
#define EPG     32000       // edges per graph
#define NZPG    48000       // framelet nnz per graph
#define BB      50          // graphs
#define NPG     2000        // nodes per graph
#define BANDS   3
#define HH      64
#define CC      10

#define GRID_BLOCKS 148
#define NTILES  ((NN + 63) / 64)   // 1563

// -------- scratch (static device globals) --------
__device__ float g_bufA[NN * HH];
__device__ float g_bufB[NN * HH];
__device__ float g_dinv[NN];
__device__ int   g_rowptr[NN + 1];
__device__ int   g_cols[EE];
__device__ float g_wnode[NN * BANDS];

// -------- grid barrier state --------
__device__ unsigned g_arrive = 0;
__device__ volatile unsigned g_gen = 0;

__device__ __forceinline__ void grid_sync() {
    __syncthreads();
    if (threadIdx.x == 0) {
        unsigned gen = g_gen;
        __threadfence();
        if (atomicAdd(&g_arrive, 1) == GRID_BLOCKS - 1) {
            atomicExch(&g_arrive, 0);
            __threadfence();
            g_gen = gen + 1;
        } else {
            while (g_gen == gen) { __nanosleep(32); }
        }
        __threadfence();
    }
    __syncthreads();
}

// -------- shared memory union across phases --------
union SmemU {
    struct { int cnt[NPG]; int wsum[32]; } build;          // ~8.1 KB
    float fw[NPG * BANDS];                                 // 24 KB
    struct { float Ws[64][64]; float As[64][65]; } gm;     // 32.6 KB
    struct { float part[16][3][64]; float xp[192]; float hid[64]; } ph; // 13.3 KB
};

// ---------------- per-graph CSR build (one block) ----------------
__device__ void build_phase(SmemU& sm, int g, const int* __restrict__ row,
                            const int* __restrict__ col) {
    int t = threadIdx.x;
    int nbase = g * NPG;
    int ebase = g * EPG;

    for (int i = t; i < NPG; i += 1024) sm.build.cnt[i] = 0;
    __syncthreads();
    for (int e = ebase + t; e < ebase + EPG; e += 1024)
        atomicAdd(&sm.build.cnt[row[e] - nbase], 1);
    __syncthreads();

    // pair-per-thread exclusive scan over 2000 counters
    int a = 0, b = 0;
    if (t < 1000) { a = sm.build.cnt[2 * t]; b = sm.build.cnt[2 * t + 1]; }
    int lane = t & 31, wid = t >> 5;
    int s = a + b;
    int inc = s;
#pragma unroll
    for (int o = 1; o < 32; o <<= 1) {
        int v = __shfl_up_sync(0xffffffffu, inc, o);
        if (lane >= o) inc += v;
    }
    if (lane == 31) sm.build.wsum[wid] = inc;
    __syncthreads();
    if (wid == 0) {
        int w = sm.build.wsum[lane];
#pragma unroll
        for (int o = 1; o < 32; o <<= 1) {
            int v = __shfl_up_sync(0xffffffffu, w, o);
            if (lane >= o) w += v;
        }
        sm.build.wsum[lane] = w;   // inclusive warp sums
    }
    __syncthreads();
    int wbase = (wid > 0) ? sm.build.wsum[wid - 1] : 0;
    int excl = wbase + inc - s;    // exclusive offset of this pair
    __syncthreads();               // all cnt reads done before overwrite
    if (t < 1000) {
        int o0 = excl, o1 = excl + a;
        sm.build.cnt[2 * t]     = o0;
        sm.build.cnt[2 * t + 1] = o1;
        g_rowptr[nbase + 2 * t]     = ebase + o0;
        g_rowptr[nbase + 2 * t + 1] = ebase + o1;
        g_dinv[nbase + 2 * t]     = rsqrtf((float)(a + 1));
        g_dinv[nbase + 2 * t + 1] = rsqrtf((float)(b + 1));
    }
    if (g == 0 && t == 0) g_rowptr[NN] = EE;
    __syncthreads();
    // scatter
    for (int e = ebase + t; e < ebase + EPG; e += 1024) {
        int r = row[e] - nbase;
        int p = atomicAdd(&sm.build.cnt[r], 1);
        g_cols[ebase + p] = col[e];
    }
}

// ---------------- per-graph framelet weight table ----------------
__device__ void frame_phase(SmemU& sm, int g, const int* __restrict__ fr,
                            const int* __restrict__ fc, const float* __restrict__ fv,
                            const int* __restrict__ dix) {
    int t = threadIdx.x;
    for (int i = t; i < NPG * BANDS; i += 1024) sm.fw[i] = 0.0f;
    __syncthreads();
    int base = g * NZPG;
    int nbase = g * NPG;
    for (int e = base + t; e < base + NZPG; e += 1024) {
        int r = fr[e];
        int c = fc[e] - nbase;
        float v = fv[e];
        int band = dix[r];
        atomicAdd(&sm.fw[c * BANDS + band], v);
    }
    __syncthreads();
    int obase = g * NPG * BANDS;
    for (int i = t; i < NPG * BANDS; i += 1024) g_wnode[obase + i] = sm.fw[i];
}

// ---------------- GEMM: C = A[N,64] @ W[64,64] over tile range ----------------
__device__ void gemm_phase(SmemU& sm, const float* __restrict__ A,
                           const float* __restrict__ W, float* __restrict__ C,
                           int tile0, int tstride) {
    int t = threadIdx.x;
    for (int idx = t; idx < 4096; idx += 1024)
        sm.gm.Ws[idx >> 6][idx & 63] = W[idx];
    int tx = t & 15, ty = t >> 4;
    for (int tile = tile0; tile < NTILES; tile += tstride) {
        int r0 = tile * 64;
        __syncthreads();
        for (int idx = t; idx < 4096; idx += 1024) {
            int r = idx >> 6, k = idx & 63;
            int gr = r0 + r;
            sm.gm.As[k][r] = (gr < NN) ? A[gr * 64 + k] : 0.0f;
        }
        __syncthreads();
        float a0 = 0.f, a1 = 0.f, a2 = 0.f, a3 = 0.f;
#pragma unroll
        for (int k = 0; k < 64; k++) {
            float av = sm.gm.As[k][ty];
            float4 w4 = *(const float4*)&sm.gm.Ws[k][tx * 4];
            a0 += av * w4.x; a1 += av * w4.y; a2 += av * w4.z; a3 += av * w4.w;
        }
        int gr = r0 + ty;
        if (gr < NN) *(float4*)&C[gr * 64 + tx * 4] = make_float4(a0, a1, a2, a3);
    }
}

// ------- GCN aggregation: warp per row, strided over all rows -------
__device__ void agg_phase(const float* __restrict__ h, const float* __restrict__ bias,
                          float* __restrict__ out) {
    int gw = (blockIdx.x * 1024 + threadIdx.x) >> 5;
    int lane = threadIdx.x & 31;
    const int nwarps = GRID_BLOCKS * 32;
    const float2* h2 = (const float2*)h;
    float bx = bias[lane * 2];
    float by = bias[lane * 2 + 1];
    for (int r = gw; r < NN; r += nwarps) {
        float dr = g_dinv[r];
        float2 hv = h2[r * 32 + lane];
        float ax = dr * hv.x, ay = dr * hv.y;
        int e0 = g_rowptr[r], e1 = g_rowptr[r + 1];
        int e = e0;
        for (; e + 4 <= e1; e += 4) {
            int c0 = g_cols[e], c1 = g_cols[e + 1], c2 = g_cols[e + 2], c3 = g_cols[e + 3];
            float d0 = g_dinv[c0], d1 = g_dinv[c1], d2 = g_dinv[c2], d3 = g_dinv[c3];
            float2 h0 = h2[c0 * 32 + lane];
            float2 h1 = h2[c1 * 32 + lane];
            float2 hc2 = h2[c2 * 32 + lane];
            float2 hc3 = h2[c3 * 32 + lane];
            ax += d0 * h0.x + d1 * h1.x + d2 * hc2.x + d3 * hc3.x;
            ay += d0 * h0.y + d1 * h1.y + d2 * hc2.y + d3 * hc3.y;
        }
        for (; e < e1; e++) {
            int c = g_cols[e];
            float dc = g_dinv[c];
            float2 hc = h2[c * 32 + lane];
            ax += dc * hc.x;
            ay += dc * hc.y;
        }
        ((float2*)out)[r * 32 + lane] =
            make_float2(fmaxf(dr * ax + bx, 0.0f), fmaxf(dr * ay + by, 0.0f));
    }
}

// ------- fused pool + head for one graph (one block) -------
__device__ void poolhead_phase(SmemU& sm, int g, const float* __restrict__ h,
                               const float* __restrict__ fcW1, const float* __restrict__ fcb1,
                               const float* __restrict__ fcW2, const float* __restrict__ fcb2,
                               float* __restrict__ out) {
    int t = threadIdx.x;
    int f = t & 63, sub = t >> 6;   // 16 subs of 64 threads
    float a0 = 0.f, a1 = 0.f, a2 = 0.f;
    int base = g * NPG;
    for (int j = base + sub; j < base + NPG; j += 16) {
        float w0 = g_wnode[j * 3 + 0];
        float w1 = g_wnode[j * 3 + 1];
        float w2 = g_wnode[j * 3 + 2];
        float hv = h[j * 64 + f];
        a0 += w0 * hv; a1 += w1 * hv; a2 += w2 * hv;
    }
    sm.ph.part[sub][0][f] = a0;
    sm.ph.part[sub][1][f] = a1;
    sm.ph.part[sub][2][f] = a2;
    __syncthreads();
    if (t < 192) {
        float s = 0.f;
#pragma unroll
        for (int p = 0; p < 16; p++) s += sm.ph.part[p][t >> 6][t & 63];
        sm.ph.xp[t] = s;
    }
    __syncthreads();
    if (t < HH) {
        float acc = fcb1[t];
#pragma unroll 8
        for (int k = 0; k < BANDS * HH; k++) acc += sm.ph.xp[k] * fcW1[k * HH + t];
        sm.ph.hid[t] = fmaxf(acc, 0.0f);
    }
    __syncthreads();
    if (t < CC) {
        float o = fcb2[t];
#pragma unroll
        for (int k = 0; k < HH; k++) o += sm.ph.hid[k] * fcW2[k * CC + t];
        out[g * CC + t] = o;
    }
}

// ---------------- the mega-kernel ----------------
__global__ void __launch_bounds__(1024, 1)
k_mega(const float* __restrict__ x, const int* __restrict__ row, const int* __restrict__ col,
       const int* __restrict__ fr, const int* __restrict__ fc, const float* __restrict__ fv,
       const int* __restrict__ dix,
       const float* __restrict__ W1, const float* __restrict__ b1,
       const float* __restrict__ W2, const float* __restrict__ b2,
       const float* __restrict__ fcW1, const float* __restrict__ fcb1,
       const float* __restrict__ fcW2, const float* __restrict__ fcb2,
       float* __restrict__ out) {
    __shared__ SmemU sm;
    int bid = blockIdx.x;

    // P0: CSR build (0-49) | framelet weights (50-99) | GEMM1 (100-147)
    if (bid < BB) {
        build_phase(sm, bid, row, col);
    } else if (bid < 2 * BB) {
        frame_phase(sm, bid - BB, fr, fc, fv, dix);
    } else {
        gemm_phase(sm, x, W1, g_bufA, bid - 2 * BB, GRID_BLOCKS - 2 * BB);
    }
    grid_sync();

    // P1: aggregation layer 1
    agg_phase(g_bufA, b1, g_bufB);
    grid_sync();

    // P2: GEMM2 (all blocks)
    gemm_phase(sm, g_bufB, W2, g_bufA, bid, GRID_BLOCKS);
    grid_sync();

    // P3: aggregation layer 2
    agg_phase(g_bufA, b2, g_bufB);
    grid_sync();

    // P4: fused pool + MLP head
    if (bid < BB)
        poolhead_phase(sm, bid, g_bufB, fcW1, fcb1, fcW2, fcb2, out);
}

extern "C" void kernel_launch(void* const* d_in, const int* in_sizes, int n_in,
                              void* d_out, int out_size) {
    (void)in_sizes; (void)n_in; (void)out_size;
    const float* x    = (const float*)d_in[0];
    const int*   ei   = (const int*)d_in[1];
    const int*   frow = (const int*)d_in[3];
    const int*   fcol = (const int*)d_in[4];
    const float* fval = (const float*)d_in[5];
    const int*   dix  = (const int*)d_in[6];
    const float* W1   = (const float*)d_in[8];
    const float* b1   = (const float*)d_in[9];
    const float* W2   = (const float*)d_in[10];
    const float* b2   = (const float*)d_in[11];
    const float* fcW1 = (const float*)d_in[12];
    const float* fcb1 = (const float*)d_in[13];
    const float* fcW2 = (const float*)d_in[14];
    const float* fcb2 = (const float*)d_in[15];
    float* out = (float*)d_out;

    const int* row = ei;        // edge_index[0]
    const int* col = ei + EE;   // edge_index[1]

    k_mega<<<GRID_BLOCKS, 1024>>>(x, row, col, frow, fcol, fval, dix,
                                  W1, b1, W2, b2, fcW1, fcb1, fcW2, fcb2, out);
}

// round 11
// speedup vs baseline: 24.4222x; 2.1004x over previous
#include <cuda_runtime.h>
#include <cuda_bf16.h>

// Fixed problem shapes
#define NN      100000      // total nodes
#define EE      1600000     // total edges
#define EPG     32000       // edges per graph
#define NZPG    48000       // framelet nnz per graph
#define BB      50          // graphs
#define NPG     2000        // nodes per graph
#define BANDS   3
#define HH      64
#define CC      10

#define GRID_BLOCKS 148
#define TILE_R  128
#define NT128   ((NN + TILE_R - 1) / TILE_R)   // 782
#define CHUNK   4

// -------- scratch (static device globals) --------
__device__ float g_bufA[NN * HH];
__device__ float g_bufB[NN * HH];
__device__ float g_dinv[NN];
__device__ int   g_rowptr[NN + 1];
__device__ int   g_cols[EE];
__device__ float g_wnode[NN * BANDS];
__device__ int   g_ctr1 = 0;            // gemm1 work-steal counter
__device__ int   g_ticket[GRID_BLOCKS]; // per-block ticket broadcast

// -------- grid barrier state --------
__device__ unsigned g_arrive = 0;
__device__ volatile unsigned g_gen = 0;

__device__ __forceinline__ void grid_sync() {
    __syncthreads();
    if (threadIdx.x == 0) {
        unsigned gen = g_gen;
        __threadfence();
        if (atomicAdd(&g_arrive, 1) == GRID_BLOCKS - 1) {
            atomicExch(&g_arrive, 0);
            __threadfence();
            g_gen = gen + 1;
        } else {
            while (g_gen == gen) { __nanosleep(32); }
        }
        __threadfence();
    }
    __syncthreads();
}

// -------- shared memory union across phases (48KB) --------
union SmemU {
    struct { int cnt[NPG]; int wsum[32]; } build;              // ~8.1 KB
    float fw[NPG * BANDS];                                     // 24 KB
    struct { float Ws[64][64]; float As[TILE_R][64]; } gm;     // 48 KB
    struct { float part[16][3][64]; float xp[192]; float hid[64]; } ph; // 13.3 KB
};

// ---------------- per-graph CSR build (one block) ----------------
__device__ void build_phase(SmemU& sm, int g, const int* __restrict__ row,
                            const int* __restrict__ col) {
    int t = threadIdx.x;
    int nbase = g * NPG;
    int ebase = g * EPG;

    for (int i = t; i < NPG; i += 1024) sm.build.cnt[i] = 0;
    __syncthreads();
    for (int e = ebase + t; e < ebase + EPG; e += 1024)
        atomicAdd(&sm.build.cnt[row[e] - nbase], 1);
    __syncthreads();

    // pair-per-thread exclusive scan over 2000 counters
    int a = 0, b = 0;
    if (t < 1000) { a = sm.build.cnt[2 * t]; b = sm.build.cnt[2 * t + 1]; }
    int lane = t & 31, wid = t >> 5;
    int s = a + b;
    int inc = s;
#pragma unroll
    for (int o = 1; o < 32; o <<= 1) {
        int v = __shfl_up_sync(0xffffffffu, inc, o);
        if (lane >= o) inc += v;
    }
    if (lane == 31) sm.build.wsum[wid] = inc;
    __syncthreads();
    if (wid == 0) {
        int w = sm.build.wsum[lane];
#pragma unroll
        for (int o = 1; o < 32; o <<= 1) {
            int v = __shfl_up_sync(0xffffffffu, w, o);
            if (lane >= o) w += v;
        }
        sm.build.wsum[lane] = w;
    }
    __syncthreads();
    int wbase = (wid > 0) ? sm.build.wsum[wid - 1] : 0;
    int excl = wbase + inc - s;
    __syncthreads();
    if (t < 1000) {
        int o0 = excl, o1 = excl + a;
        sm.build.cnt[2 * t]     = o0;
        sm.build.cnt[2 * t + 1] = o1;
        g_rowptr[nbase + 2 * t]     = ebase + o0;
        g_rowptr[nbase + 2 * t + 1] = ebase + o1;
        g_dinv[nbase + 2 * t]     = rsqrtf((float)(a + 1));
        g_dinv[nbase + 2 * t + 1] = rsqrtf((float)(b + 1));
    }
    if (g == 0 && t == 0) g_rowptr[NN] = EE;
    __syncthreads();
    for (int e = ebase + t; e < ebase + EPG; e += 1024) {
        int r = row[e] - nbase;
        int p = atomicAdd(&sm.build.cnt[r], 1);
        g_cols[ebase + p] = col[e];
    }
    __syncthreads();   // REQUIRED: smem union is re-used (GEMM Ws) right after
}

// ---------------- per-graph framelet weight table ----------------
__device__ void frame_phase(SmemU& sm, int g, const int* __restrict__ fr,
                            const int* __restrict__ fc, const float* __restrict__ fv,
                            const int* __restrict__ dix) {
    int t = threadIdx.x;
    for (int i = t; i < NPG * BANDS; i += 1024) sm.fw[i] = 0.0f;
    __syncthreads();
    int base = g * NZPG;
    int nbase = g * NPG;
    for (int e = base + t; e < base + NZPG; e += 1024) {
        int r = fr[e];
        int c = fc[e] - nbase;
        float v = fv[e];
        int band = dix[r];
        atomicAdd(&sm.fw[c * BANDS + band], v);
    }
    __syncthreads();
    int obase = g * NPG * BANDS;
    for (int i = t; i < NPG * BANDS; i += 1024) g_wnode[obase + i] = sm.fw[i];
    __syncthreads();   // REQUIRED: smem union is re-used (GEMM Ws) right after
}

// -------- one 128x64 GEMM tile: C[r,:] = dinv[r] * (A[r,:] @ W) --------
__device__ __forceinline__ void gemm_tile(SmemU& sm, const float* __restrict__ A,
                                          float* __restrict__ C, int tile) {
    int t = threadIdx.x;
    int r0 = tile * TILE_R;
    __syncthreads();
#pragma unroll
    for (int i = 0; i < 8; i++) {
        int idx = t + i * 1024;
        int r = idx >> 6, k = idx & 63;
        int gr = r0 + r;
        sm.gm.As[r][k] = (gr < NN) ? A[gr * 64 + k] : 0.0f;
    }
    __syncthreads();
    int tx = t & 15, ty = t >> 4;   // ty: 0..63 -> rows ty, ty+64
    float a00 = 0.f, a01 = 0.f, a02 = 0.f, a03 = 0.f;
    float a10 = 0.f, a11 = 0.f, a12 = 0.f, a13 = 0.f;
#pragma unroll
    for (int k = 0; k < 64; k++) {
        float4 w4 = *(const float4*)&sm.gm.Ws[k][tx * 4];
        float av0 = sm.gm.As[ty][k];
        float av1 = sm.gm.As[ty + 64][k];
        a00 += av0 * w4.x; a01 += av0 * w4.y; a02 += av0 * w4.z; a03 += av0 * w4.w;
        a10 += av1 * w4.x; a11 += av1 * w4.y; a12 += av1 * w4.z; a13 += av1 * w4.w;
    }
    int gr0 = r0 + ty, gr1 = r0 + ty + 64;
    if (gr0 < NN) {
        float d = g_dinv[gr0];
        *(float4*)&C[gr0 * 64 + tx * 4] = make_float4(d * a00, d * a01, d * a02, d * a03);
    }
    if (gr1 < NN) {
        float d = g_dinv[gr1];
        *(float4*)&C[gr1 * 64 + tx * 4] = make_float4(d * a10, d * a11, d * a12, d * a13);
    }
}

__device__ void load_W(SmemU& sm, const float* __restrict__ W) {
    for (int idx = threadIdx.x; idx < 4096; idx += 1024)
        sm.gm.Ws[idx >> 6][idx & 63] = W[idx];
}

// gemm2: static stride (epilogue pre-scales by dinv)
__device__ void gemm_static(SmemU& sm, const float* __restrict__ A,
                            const float* __restrict__ W, float* __restrict__ C) {
    load_W(sm, W);
    for (int tile = blockIdx.x; tile < NT128; tile += GRID_BLOCKS)
        gemm_tile(sm, A, C, tile);
}

// ------- GCN aggregation: warp per row; input pre-scaled by dinv -------
__device__ void agg_phase(const float* __restrict__ hd, const float* __restrict__ bias,
                          float* __restrict__ out) {
    int gw = (blockIdx.x * 1024 + threadIdx.x) >> 5;
    int lane = threadIdx.x & 31;
    const int nwarps = GRID_BLOCKS * 32;
    const float2* h2 = (const float2*)hd;
    float bx = bias[lane * 2];
    float by = bias[lane * 2 + 1];
    for (int r = gw; r < NN; r += nwarps) {
        float dr = g_dinv[r];
        float2 hv = h2[r * 32 + lane];     // self loop (already *dinv[r])
        float ax = hv.x, ay = hv.y;
        int e0 = g_rowptr[r], e1 = g_rowptr[r + 1];
        int e = e0;
        for (; e + 8 <= e1; e += 8) {
            int cc[8];
            float2 hh[8];
#pragma unroll
            for (int i = 0; i < 8; i++) cc[i] = g_cols[e + i];
#pragma unroll
            for (int i = 0; i < 8; i++) hh[i] = h2[cc[i] * 32 + lane];
#pragma unroll
            for (int i = 0; i < 8; i++) { ax += hh[i].x; ay += hh[i].y; }
        }
        for (; e < e1; e++) {
            float2 hc = h2[g_cols[e] * 32 + lane];
            ax += hc.x;
            ay += hc.y;
        }
        ((float2*)out)[r * 32 + lane] =
            make_float2(fmaxf(dr * ax + bx, 0.0f), fmaxf(dr * ay + by, 0.0f));
    }
}

// ------- fused pool + head for one graph (one block) -------
__device__ void poolhead_phase(SmemU& sm, int g, const float* __restrict__ h,
                               const float* __restrict__ fcW1, const float* __restrict__ fcb1,
                               const float* __restrict__ fcW2, const float* __restrict__ fcb2,
                               float* __restrict__ out) {
    int t = threadIdx.x;
    int f = t & 63, sub = t >> 6;   // 16 subs of 64 threads
    float a0 = 0.f, a1 = 0.f, a2 = 0.f;
    int base = g * NPG;
    for (int j = base + sub; j < base + NPG; j += 16) {
        float w0 = g_wnode[j * 3 + 0];
        float w1 = g_wnode[j * 3 + 1];
        float w2 = g_wnode[j * 3 + 2];
        float hv = h[j * 64 + f];
        a0 += w0 * hv; a1 += w1 * hv; a2 += w2 * hv;
    }
    __syncthreads();   // prior phase smem use (gemm) done before overwrite
    sm.ph.part[sub][0][f] = a0;
    sm.ph.part[sub][1][f] = a1;
    sm.ph.part[sub][2][f] = a2;
    __syncthreads();
    if (t < 192) {
        float s = 0.f;
#pragma unroll
        for (int p = 0; p < 16; p++) s += sm.ph.part[p][t >> 6][t & 63];
        sm.ph.xp[t] = s;
    }
    __syncthreads();
    if (t < HH) {
        float acc = fcb1[t];
#pragma unroll 8
        for (int k = 0; k < BANDS * HH; k++) acc += sm.ph.xp[k] * fcW1[k * HH + t];
        sm.ph.hid[t] = fmaxf(acc, 0.0f);
    }
    __syncthreads();
    if (t < CC) {
        float o = fcb2[t];
#pragma unroll
        for (int k = 0; k < HH; k++) o += sm.ph.hid[k] * fcW2[k * CC + t];
        out[g * CC + t] = o;
    }
}

// ---------------- the mega-kernel ----------------
__global__ void __launch_bounds__(1024, 1)
k_mega(const float* __restrict__ x, const int* __restrict__ row, const int* __restrict__ col,
       const int* __restrict__ fr, const int* __restrict__ fc, const float* __restrict__ fv,
       const int* __restrict__ dix,
       const float* __restrict__ W1, const float* __restrict__ b1,
       const float* __restrict__ W2, const float* __restrict__ b2,
       const float* __restrict__ fcW1, const float* __restrict__ fcb1,
       const float* __restrict__ fcW2, const float* __restrict__ fcb2,
       float* __restrict__ out) {
    __shared__ SmemU sm;
    int bid = blockIdx.x;

    // P0: build (0-49) | frame (50-99) first; then ALL blocks converge on
    // GEMM1 via work-stealing. GEMM1 stores the RAW product (no dinv scaling,
    // since build may still be running on other blocks); layer-1 aggregation
    // applies dinv[c] on read.
    if (bid < BB) {
        build_phase(sm, bid, row, col);
    } else if (bid < 2 * BB) {
        frame_phase(sm, bid - BB, fr, fc, fv, dix);
    }
    {
        load_W(sm, W1);
        for (;;) {
            __syncthreads();
            if (threadIdx.x == 0)
                g_ticket[blockIdx.x] = atomicAdd(&g_ctr1, CHUNK);
            __syncthreads();
            int t0 = g_ticket[blockIdx.x];
            if (t0 >= NT128) break;
            int t1 = min(t0 + CHUNK, NT128);
            for (int tile = t0; tile < t1; tile++) {
                int t = threadIdx.x;
                int r0 = tile * TILE_R;
                __syncthreads();
#pragma unroll
                for (int i = 0; i < 8; i++) {
                    int idx = t + i * 1024;
                    int r = idx >> 6, k = idx & 63;
                    int gr = r0 + r;
                    sm.gm.As[r][k] = (gr < NN) ? x[gr * 64 + k] : 0.0f;
                }
                __syncthreads();
                int tx = t & 15, ty = t >> 4;
                float a00 = 0.f, a01 = 0.f, a02 = 0.f, a03 = 0.f;
                float a10 = 0.f, a11 = 0.f, a12 = 0.f, a13 = 0.f;
#pragma unroll
                for (int k = 0; k < 64; k++) {
                    float4 w4 = *(const float4*)&sm.gm.Ws[k][tx * 4];
                    float av0 = sm.gm.As[ty][k];
                    float av1 = sm.gm.As[ty + 64][k];
                    a00 += av0 * w4.x; a01 += av0 * w4.y; a02 += av0 * w4.z; a03 += av0 * w4.w;
                    a10 += av1 * w4.x; a11 += av1 * w4.y; a12 += av1 * w4.z; a13 += av1 * w4.w;
                }
                int gr0 = r0 + ty, gr1 = r0 + ty + 64;
                if (gr0 < NN)
                    *(float4*)&g_bufA[gr0 * 64 + tx * 4] = make_float4(a00, a01, a02, a03);
                if (gr1 < NN)
                    *(float4*)&g_bufA[gr1 * 64 + tx * 4] = make_float4(a10, a11, a12, a13);
            }
        }
    }
    grid_sync();
    if (bid == GRID_BLOCKS - 1 && threadIdx.x == 0) g_ctr1 = 0;  // reset for graph replay

    // P1: aggregation layer 1 -- raw h, scale by dinv[c] on read
    {
        int gw = (bid * 1024 + threadIdx.x) >> 5;
        int lane = threadIdx.x & 31;
        const int nwarps = GRID_BLOCKS * 32;
        const float2* h2 = (const float2*)g_bufA;
        float bx = b1[lane * 2];
        float by = b1[lane * 2 + 1];
        for (int r = gw; r < NN; r += nwarps) {
            float dr = g_dinv[r];
            float2 hv = h2[r * 32 + lane];
            float ax = dr * hv.x, ay = dr * hv.y;
            int e0 = g_rowptr[r], e1 = g_rowptr[r + 1];
            int e = e0;
            for (; e + 8 <= e1; e += 8) {
                int cc[8];
                float dd[8];
                float2 hh[8];
#pragma unroll
                for (int i = 0; i < 8; i++) cc[i] = g_cols[e + i];
#pragma unroll
                for (int i = 0; i < 8; i++) { dd[i] = g_dinv[cc[i]]; hh[i] = h2[cc[i] * 32 + lane]; }
#pragma unroll
                for (int i = 0; i < 8; i++) { ax += dd[i] * hh[i].x; ay += dd[i] * hh[i].y; }
            }
            for (; e < e1; e++) {
                int c = g_cols[e];
                float dc = g_dinv[c];
                float2 hc = h2[c * 32 + lane];
                ax += dc * hc.x;
                ay += dc * hc.y;
            }
            ((float2*)g_bufB)[r * 32 + lane] =
                make_float2(fmaxf(dr * ax + bx, 0.0f), fmaxf(dr * ay + by, 0.0f));
        }
    }
    grid_sync();

    // P2: GEMM2 (static partition), epilogue pre-scales by dinv
    gemm_static(sm, g_bufB, W2, g_bufA);
    grid_sync();

    // P3: aggregation layer 2 (input pre-scaled)
    agg_phase(g_bufA, b2, g_bufB);
    grid_sync();

    // P4: fused pool + MLP head
    if (bid < BB)
        poolhead_phase(sm, bid, g_bufB, fcW1, fcb1, fcW2, fcb2, out);
}

extern "C" void kernel_launch(void* const* d_in, const int* in_sizes, int n_in,
                              void* d_out, int out_size) {
    (void)in_sizes; (void)n_in; (void)out_size;
    const float* x    = (const float*)d_in[0];
    const int*   ei   = (const int*)d_in[1];
    const int*   frow = (const int*)d_in[3];
    const int*   fcol = (const int*)d_in[4];
    const float* fval = (const float*)d_in[5];
    const int*   dix  = (const int*)d_in[6];
    const float* W1   = (const float*)d_in[8];
    const float* b1   = (const float*)d_in[9];
    const float* W2   = (const float*)d_in[10];
    const float* b2   = (const float*)d_in[11];
    const float* fcW1 = (const float*)d_in[12];
    const float* fcb1 = (const float*)d_in[13];
    const float* fcW2 = (const float*)d_in[14];
    const float* fcb2 = (const float*)d_in[15];
    float* out = (float*)d_out;

    const int* row = ei;        // edge_index[0]
    const int* col = ei + EE;   // edge_index[1]

    k_mega<<<GRID_BLOCKS, 1024>>>(x, row, col, frow, fcol, fval, dix,
                                  W1, b1, W2, b2, fcW1, fcb1, fcW2, fcb2, out);
}